// round 1
// baseline (speedup 1.0000x reference)
#include <cuda_runtime.h>

// Problem constants (fixed shapes: v, v_pred are [4, 8192, 3] fp32)
#define BATCH 4
#define NPTS  8192
#define JS    8                 // reduction-dim splits
#define SEG   (NPTS / JS)       // 1024 y-points per segment
#define XC    8                 // x chunks per batch
#define T1    256               // threads, kernel 1
#define XPT   4                 // query points per thread (register tile)

// Partial mins: [BATCH][JS][NPTS]. 1 MB static device scratch (no allocs).
__device__ float g_partial[BATCH * JS * NPTS];

// ---------------------------------------------------------------------------
// Kernel 1: for each (batch, x-chunk, y-segment) compute per-query partial min
// of (|y|^2 - 2 x.y) over the segment; add |x|^2 at the end (hoisted out of
// the min since it is constant per query point).
// Inner loop: 1 broadcast LDS.128 + (3 FFMA + 1 FMNMX) * XPT.
// ---------------------------------------------------------------------------
__global__ __launch_bounds__(T1) void chamfer_partial_kernel(
    const float* __restrict__ v,       // y / target  [B, N, 3]
    const float* __restrict__ v_pred)  // x / queries [B, N, 3]
{
    __shared__ float4 ys[SEG];

    const int blk = blockIdx.x;           // 0 .. B*XC*JS-1 = 255
    const int b   = blk >> 6;             // / (XC*JS)
    const int rem = blk & 63;
    const int xc  = rem >> 3;
    const int js  = rem & 7;

    const float* __restrict__ yb = v      + (size_t)b * NPTS * 3;
    const float* __restrict__ xb = v_pred + (size_t)b * NPTS * 3;

    // Stage y segment into smem as (y0, y1, y2, |y|^2)
    for (int t = threadIdx.x; t < SEG; t += T1) {
        const int j = js * SEG + t;
        const float y0 = __ldg(&yb[j * 3 + 0]);
        const float y1 = __ldg(&yb[j * 3 + 1]);
        const float y2 = __ldg(&yb[j * 3 + 2]);
        ys[t] = make_float4(y0, y1, y2, fmaf(y0, y0, fmaf(y1, y1, y2 * y2)));
    }
    __syncthreads();

    // Register-tile XPT query points
    float a0[XPT], a1[XPT], a2[XPT], c[XPT], m[XPT];
    const int i0 = xc * (T1 * XPT) + threadIdx.x;
#pragma unroll
    for (int k = 0; k < XPT; k++) {
        const int i = i0 + k * T1;
        const float p0 = __ldg(&xb[i * 3 + 0]);
        const float p1 = __ldg(&xb[i * 3 + 1]);
        const float p2 = __ldg(&xb[i * 3 + 2]);
        a0[k] = -2.0f * p0;
        a1[k] = -2.0f * p1;
        a2[k] = -2.0f * p2;
        c[k]  = fmaf(p0, p0, fmaf(p1, p1, p2 * p2));
        m[k]  = 3.402823466e38f;
    }

#pragma unroll 4
    for (int j = 0; j < SEG; j++) {
        const float4 y = ys[j];
#pragma unroll
        for (int k = 0; k < XPT; k++) {
            const float d = fmaf(a0[k], y.x,
                            fmaf(a1[k], y.y,
                            fmaf(a2[k], y.z, y.w)));
            m[k] = fminf(m[k], d);
        }
    }

    float* __restrict__ out = g_partial + (size_t)(b * JS + js) * NPTS;
#pragma unroll
    for (int k = 0; k < XPT; k++)
        out[i0 + k * T1] = m[k] + c[k];   // coalesced
}

// ---------------------------------------------------------------------------
// Kernel 2: single deterministic block. Min across the JS segment-partials per
// query point, then mean over all B*NPTS points. float4 loads (L2-resident).
// ---------------------------------------------------------------------------
__global__ __launch_bounds__(1024) void chamfer_reduce_kernel(float* __restrict__ out)
{
    const int t = threadIdx.x;                 // 0..1023
    float sum = 0.0f;

    // 32768 points = 8 groups x (1024 threads x 4 consecutive points)
#pragma unroll
    for (int g = 0; g < 8; g++) {
        const int p = g * 4096 + t * 4;        // flattened (b*NPTS + i), 4-aligned
        const int b = p >> 13;                 // NPTS = 8192 = 2^13
        const int i = p & (NPTS - 1);
        float4 mn = make_float4(3.402823466e38f, 3.402823466e38f,
                                3.402823466e38f, 3.402823466e38f);
#pragma unroll
        for (int js = 0; js < JS; js++) {
            const float4 q = *reinterpret_cast<const float4*>(
                &g_partial[((size_t)(b * JS + js) << 13) + i]);
            mn.x = fminf(mn.x, q.x);
            mn.y = fminf(mn.y, q.y);
            mn.z = fminf(mn.z, q.z);
            mn.w = fminf(mn.w, q.w);
        }
        sum += (mn.x + mn.y) + (mn.z + mn.w);
    }

    // Block reduction: warp shuffles, then one warp over 32 partials.
#pragma unroll
    for (int o = 16; o > 0; o >>= 1)
        sum += __shfl_down_sync(0xffffffffu, sum, o);

    __shared__ float ws[32];
    const int lane = t & 31;
    const int wid  = t >> 5;
    if (lane == 0) ws[wid] = sum;
    __syncthreads();

    if (wid == 0) {
        float s = ws[lane];
#pragma unroll
        for (int o = 16; o > 0; o >>= 1)
            s += __shfl_down_sync(0xffffffffu, s, o);
        if (lane == 0)
            out[0] = s * (1.0f / (float)(BATCH * NPTS));
    }
}

// ---------------------------------------------------------------------------
extern "C" void kernel_launch(void* const* d_in, const int* in_sizes, int n_in,
                              void* d_out, int out_size)
{
    const float* v      = (const float*)d_in[0];   // target set (y)
    const float* v_pred = (const float*)d_in[1];   // query set  (x)
    float* out = (float*)d_out;

    chamfer_partial_kernel<<<BATCH * XC * JS, T1>>>(v, v_pred);
    chamfer_reduce_kernel<<<1, 1024>>>(out);
}